// round 6
// baseline (speedup 1.0000x reference)
#include <cuda_runtime.h>
#include <math.h>

// Problem constants: N=4, R=16384, K=96
#define KS   96
#define KM   95                 // K-1 midpoint samples
#define RAYS (4 * 16384)        // 65536 rays

#define FULL  0xffffffffu
#define LOG2E 1.4426950408889634f

__device__ __forceinline__ float ex2f(float x) {
    float r;
    asm("ex2.approx.ftz.f32 %0, %1;" : "=f"(r) : "f"(x));
    return r;
}
__device__ __forceinline__ float lg2f(float x) {
    float r;
    asm("lg2.approx.ftz.f32 %0, %1;" : "=f"(r) : "f"(x));
    return r;
}

// TWO rays per warp; per ray, 3 chunks of 32 lanes cover samples 0..95.
//  - All loads for both rays front-batched (max MLP; keeps DRAM busy through
//    the warp's whole lifetime, not just its first phase).
//  - The 6 chunk scans (2 rays x 3 chunks) are independent and interleaved.
//  - Midpoint identity: sum_i w_i*0.5*(x_i+x_{i+1}) = 0.5*sum_j x_j*(w_j+w_{j-1});
//    final rgb = (0.5*S)*2 - 1 = S - 1.
//  - Global depth clip + NaN path are provable no-ops (convex combination of
//    the ray's own midpoints; wsum > 0 since softplus > 0, sorted deltas > 0).
__global__ void __launch_bounds__(256) render_kernel(
    const float* __restrict__ rgbs,     // [RAYS, K, 3]
    const float* __restrict__ sigmas,   // [RAYS, K]
    const float* __restrict__ depths,   // [RAYS, K]
    float* __restrict__ out_rgb,        // [RAYS, 3]
    float* __restrict__ out_depth,      // [RAYS]
    float* __restrict__ out_w)          // [RAYS, KM]
{
    int warpid = (blockIdx.x * blockDim.x + threadIdx.x) >> 5;
    int lane   = threadIdx.x & 31;
    if (warpid * 2 >= RAYS) return;

    // Front-batched loads for BOTH rays (42 independent LDGs).
    float dv[2][3], d1[2][3], sv[2][3], s1[2][3], rx[2][3], ry[2][3], rz[2][3];
    #pragma unroll
    for (int r = 0; r < 2; ++r) {
        int ray = warpid * 2 + r;
        const float* d  = depths + (size_t)ray * KS;
        const float* s  = sigmas + (size_t)ray * KS;
        const float* rg = rgbs   + (size_t)ray * KS * 3;
        #pragma unroll
        for (int c = 0; c < 3; ++c) {
            int i  = c * 32 + lane;
            int i1 = (i + 1 < KS) ? i + 1 : KS - 1;   // i==95 masked later
            dv[r][c] = d[i];   d1[r][c] = d[i1];
            sv[r][c] = s[i];   s1[r][c] = s[i1];
            rx[r][c] = rg[3 * i + 0];
            ry[r][c] = rg[3 * i + 1];
            rz[r][c] = rg[3 * i + 2];
        }
    }

    // Per-chunk alpha and scan input (shuffle-free).
    float alpha[2][3], p[2][3];
    #pragma unroll
    for (int r = 0; r < 2; ++r) {
        #pragma unroll
        for (int c = 0; c < 3; ++c) {
            bool valid = (c < 2) | (lane < 31);       // only i==95 invalid
            float delta = d1[r][c] - dv[r][c];
            float sm    = 0.5f * (sv[r][c] + s1[r][c]) - 1.0f;
            float em    = ex2f(-fabsf(sm) * LOG2E);
            float L     = fmaxf(sm, 0.0f) * LOG2E + lg2f(1.0f + em);
            alpha[r][c] = 1.0f - ex2f(-delta * L);
            p[r][c]     = valid ? (1.0f - alpha[r][c] + 1e-10f) : 1.0f;
        }
    }

    // Six independent inclusive multiplicative scans, interleaved (ILP=6).
    #pragma unroll
    for (int off = 1; off < 32; off <<= 1) {
        float v[2][3];
        #pragma unroll
        for (int r = 0; r < 2; ++r)
            #pragma unroll
            for (int c = 0; c < 3; ++c)
                v[r][c] = __shfl_up_sync(FULL, p[r][c], off);
        if (lane >= off) {
            #pragma unroll
            for (int r = 0; r < 2; ++r)
                #pragma unroll
                for (int c = 0; c < 3; ++c)
                    p[r][c] *= v[r][c];
        }
    }

    // Per-ray epilogue accumulators.
    float wsum[2], ar[2], ag[2], ab[2], ad[2];

    #pragma unroll
    for (int r = 0; r < 2; ++r) {
        int ray = warpid * 2 + r;
        float* wout = out_w + (size_t)ray * KM;

        float e0 = __shfl_up_sync(FULL, p[r][0], 1);
        float e1 = __shfl_up_sync(FULL, p[r][1], 1);
        float e2 = __shfl_up_sync(FULL, p[r][2], 1);
        if (lane == 0) { e0 = 1.0f; e1 = 1.0f; e2 = 1.0f; }
        float T0 = __shfl_sync(FULL, p[r][0], 31);
        float T1 = __shfl_sync(FULL, p[r][1], 31);

        float w0 = alpha[r][0] * e0;
        float w1 = alpha[r][1] * (T0 * e1);
        float w2 = alpha[r][2] * (T0 * T1 * e2);
        if (lane == 31) w2 = 0.0f;                    // i==95

        wout[lane]      = w0;
        wout[32 + lane] = w1;
        if (lane < 31) wout[64 + lane] = w2;

        // w_{j-1} chain for the midpoint identity.
        float wp0 = __shfl_up_sync(FULL, w0, 1);
        float wp1 = __shfl_up_sync(FULL, w1, 1);
        float wp2 = __shfl_up_sync(FULL, w2, 1);
        float b0  = __shfl_sync(FULL, w0, 31);
        float b1  = __shfl_sync(FULL, w1, 31);
        if (lane == 0) { wp0 = 0.0f; wp1 = b0; wp2 = b1; }

        float ww0 = w0 + wp0, ww1 = w1 + wp1, ww2 = w2 + wp2;
        wsum[r] = w0 + w1 + w2;
        ar[r] = ww0 * rx[r][0]; ag[r] = ww0 * ry[r][0];
        ab[r] = ww0 * rz[r][0]; ad[r] = ww0 * dv[r][0];
        ar[r] = fmaf(ww1, rx[r][1], ar[r]); ag[r] = fmaf(ww1, ry[r][1], ag[r]);
        ab[r] = fmaf(ww1, rz[r][1], ab[r]); ad[r] = fmaf(ww1, dv[r][1], ad[r]);
        ar[r] = fmaf(ww2, rx[r][2], ar[r]); ag[r] = fmaf(ww2, ry[r][2], ag[r]);
        ab[r] = fmaf(ww2, rz[r][2], ab[r]); ad[r] = fmaf(ww2, dv[r][2], ad[r]);
    }

    // Split-butterfly reduction: one xor-16 step on both rays' accumulators,
    // then lanes<16 carry ray A and lanes>=16 carry ray B through xor 8..1.
    float vs, vr, vg, vb, vd;
    {
        float sA = wsum[0] + __shfl_xor_sync(FULL, wsum[0], 16);
        float sB = wsum[1] + __shfl_xor_sync(FULL, wsum[1], 16);
        float rA = ar[0]   + __shfl_xor_sync(FULL, ar[0],   16);
        float rB = ar[1]   + __shfl_xor_sync(FULL, ar[1],   16);
        float gA = ag[0]   + __shfl_xor_sync(FULL, ag[0],   16);
        float gB = ag[1]   + __shfl_xor_sync(FULL, ag[1],   16);
        float bA = ab[0]   + __shfl_xor_sync(FULL, ab[0],   16);
        float bB = ab[1]   + __shfl_xor_sync(FULL, ab[1],   16);
        float dA = ad[0]   + __shfl_xor_sync(FULL, ad[0],   16);
        float dB = ad[1]   + __shfl_xor_sync(FULL, ad[1],   16);
        bool hi = lane >= 16;
        vs = hi ? sB : sA;  vr = hi ? rB : rA;  vg = hi ? gB : gA;
        vb = hi ? bB : bA;  vd = hi ? dB : dA;
    }
    #pragma unroll
    for (int off = 8; off; off >>= 1) {
        vs += __shfl_xor_sync(FULL, vs, off);
        vr += __shfl_xor_sync(FULL, vr, off);
        vg += __shfl_xor_sync(FULL, vg, off);
        vb += __shfl_xor_sync(FULL, vb, off);
        vd += __shfl_xor_sync(FULL, vd, off);
    }

    if (lane == 0 || lane == 16) {
        int ray = warpid * 2 + (lane >> 4);
        out_rgb[ray * 3 + 0] = vr - 1.0f;        // (0.5*S)*2 - 1
        out_rgb[ray * 3 + 1] = vg - 1.0f;
        out_rgb[ray * 3 + 2] = vb - 1.0f;
        out_depth[ray] = (0.5f * vd) / vs;       // clip/NaN path: no-op
    }
}

extern "C" void kernel_launch(void* const* d_in, const int* in_sizes, int n_in,
                              void* d_out, int out_size) {
    const float* rgbs   = (const float*)d_in[0];
    const float* sigmas = (const float*)d_in[1];
    const float* depths = (const float*)d_in[2];

    float* out = (float*)d_out;
    float* out_rgb   = out;                       // 65536*3
    float* out_depth = out + (size_t)RAYS * 3;    // 65536
    float* out_w     = out + (size_t)RAYS * 4;    // 65536*95

    // 2 rays per warp, 8 warps per block -> 16 rays per block
    int blocks = RAYS / 16;
    render_kernel<<<blocks, 256>>>(rgbs, sigmas, depths, out_rgb, out_depth, out_w);
}